// round 16
// baseline (speedup 1.0000x reference)
#include <cuda_runtime.h>
#include <cuda_fp16.h>
#include <math.h>

#define B_SZ 256
#define T_SZ 256
#define IN_DIM 64
#define HID 1024
#define DIM2 512
#define OUT_DIM 16
#define MT (B_SZ*T_SZ)   // 65536
#define G3 (3*HID)       // 3072

// ======================= scratch (device globals) ==========================
__device__ float g_gi[(size_t)MT*G3];       // 805 MB, layout [t][jt(64)][b(256)][48]
__device__ float g_hf[B_SZ*HID];            // final h (f32)
__device__ float g_o3[B_SZ*DIM2];
__device__ int   g_bar[2*T_SZ];             // per-(mt,step) barrier counters

// fold precompute scratch (fp32)
__device__ float g_fc2T[DIM2*HID];
__device__ float g_fc1T[IN_DIM*DIM2];
__device__ float g_T1[(size_t)G3*DIM2];
__device__ float g_weff[G3*IN_DIM];
__device__ float g_tvec[HID];
__device__ float g_beff[G3];
__device__ float g_zbias[DIM2];             // stays zero

// GEMM-geometry split tiles: [tile(128 rows)][stage(k/32)][plane(2)][128][40]
__device__ __align__(128) half g_int  [(size_t)512*2*10240];   // input (K=64)
__device__ __align__(128) half g_wefft[(size_t)24*2*10240];    // W_eff (K=64)
__device__ __align__(128) half g_w3t  [(size_t)4*32*10240];    // fc3_w (K=1024)
__device__ __align__(128) half g_rht  [(size_t)2*32*10240];    // relu(h)
// persistent-GRU weight layouts
__device__ __align__(128) half g_whhH[(size_t)64*32*1920];     // [jt][kt][48][40] hi
__device__ __align__(128) half g_whhL[(size_t)64*32*640];      // [jt][kt][16][40] lo (n gate)
// h split-plane ping-pong: [buf(2)][mt(2)][kt(32)][plane(2)][128][40]
__device__ __align__(128) half g_hbuf[(size_t)2*2*32*2*128*40];

// ======================= PTX helpers =======================================
__device__ __forceinline__ unsigned saddr(const void* p) {
    return (unsigned)__cvta_generic_to_shared(p);
}
#define MBAR_INIT(mb, cnt) \
    asm volatile("mbarrier.init.shared.b64 [%0], %1;" :: "r"(mb), "r"(cnt) : "memory")
#define EXPECT_TX(mb, bytes) \
    asm volatile("mbarrier.arrive.expect_tx.shared.b64 _, [%0], %1;" :: "r"(mb), "r"(bytes) : "memory")
#define BULK_G2S(dst, src, bytes, mb) \
    asm volatile("cp.async.bulk.shared::cluster.global.mbarrier::complete_tx::bytes [%0], [%1], %2, [%3];" \
        :: "r"(dst), "l"(src), "r"(bytes), "r"(mb) : "memory")
#define MBWAIT(mb, ph) do { unsigned _d = 0; while (!_d) { \
    asm volatile("{\n\t.reg .pred p;\n\t" \
        "mbarrier.try_wait.parity.acquire.cta.shared::cta.b64 p, [%1], %2, 0x989680;\n\t" \
        "selp.b32 %0, 1, 0, p;\n\t}" \
        : "=r"(_d) : "r"(mb), "r"(ph)); } } while (0)

// f32-accumulate HMMA
__device__ __forceinline__ void mma16(float* c, const unsigned* a, const unsigned* b) {
    asm volatile("mma.sync.aligned.m16n8k16.row.col.f32.f16.f16.f32 "
        "{%0,%1,%2,%3}, {%4,%5,%6,%7}, {%8,%9}, {%0,%1,%2,%3};"
        : "+f"(c[0]), "+f"(c[1]), "+f"(c[2]), "+f"(c[3])
        : "r"(a[0]), "r"(a[1]), "r"(a[2]), "r"(a[3]), "r"(b[0]), "r"(b[1]));
}
// f16-accumulate HMMA (for small correction terms)
__device__ __forceinline__ void mma16h(unsigned* c, const unsigned* a, const unsigned* b) {
    asm volatile("mma.sync.aligned.m16n8k16.row.col.f16.f16.f16.f16 "
        "{%0,%1}, {%2,%3,%4,%5}, {%6,%7}, {%0,%1};"
        : "+r"(c[0]), "+r"(c[1])
        : "r"(a[0]), "r"(a[1]), "r"(a[2]), "r"(a[3]), "r"(b[0]), "r"(b[1]));
}
__device__ __forceinline__ void ldsm4(unsigned* r, unsigned addr) {
    asm volatile("ldmatrix.sync.aligned.m8n8.x4.shared.b16 {%0,%1,%2,%3}, [%4];"
        : "=r"(r[0]), "=r"(r[1]), "=r"(r[2]), "=r"(r[3]) : "r"(addr));
}
__device__ __forceinline__ void split2(float x, half& hi, half& lo) {
    hi = __float2half_rn(x);
    lo = __float2half_rn(x - __half2float(hi));
}
__device__ __forceinline__ float corr_lo(unsigned u) {
    __half2 h = *(__half2*)&u; return __low2float(h);
}
__device__ __forceinline__ float corr_hi(unsigned u) {
    __half2 h = *(__half2*)&u; return __high2float(h);
}

// ======================= fold precompute kernels ===========================
__global__ void transpose_f32(const float* __restrict__ s, float* __restrict__ d,
                              int R, int C)
{
    __shared__ float tile[32][33];
    int c0 = blockIdx.x * 32, r0 = blockIdx.y * 32;
    int x = threadIdx.x, y = threadIdx.y;
    #pragma unroll
    for (int i = y; i < 32; i += 8)
        tile[i][x] = s[(size_t)(r0 + i) * C + c0 + x];
    __syncthreads();
    #pragma unroll
    for (int i = y; i < 32; i += 8)
        d[(size_t)(c0 + i) * R + r0 + x] = tile[x][i];
}

__global__ __launch_bounds__(256)
void gemm_nt(const float* __restrict__ A, const float* __restrict__ W,
             const float* __restrict__ bias, float* __restrict__ C,
             int M, int N, int K)
{
    __shared__ float As[16][68];
    __shared__ float Ws[16][68];
    const int tid = threadIdx.x;
    const int m0 = blockIdx.x * 64, n0 = blockIdx.y * 64;
    const int tx = tid & 15, ty = tid >> 4;
    float acc[4][4] = {};
    const int ar = tid >> 2;
    const int ak = (tid & 3) * 4;
    const float* Aptr = A + (size_t)(m0 + ar) * K + ak;
    const float* Wptr = W + (size_t)(n0 + ar) * K + ak;
    for (int k0 = 0; k0 < K; k0 += 16) {
        float4 av = *(const float4*)(Aptr + k0);
        float4 wv = *(const float4*)(Wptr + k0);
        As[ak+0][ar] = av.x; As[ak+1][ar] = av.y; As[ak+2][ar] = av.z; As[ak+3][ar] = av.w;
        Ws[ak+0][ar] = wv.x; Ws[ak+1][ar] = wv.y; Ws[ak+2][ar] = wv.z; Ws[ak+3][ar] = wv.w;
        __syncthreads();
        #pragma unroll
        for (int k = 0; k < 16; k++) {
            float4 a = *(const float4*)&As[k][ty*4];
            float4 w = *(const float4*)&Ws[k][tx*4];
            float avv[4] = {a.x, a.y, a.z, a.w};
            float wvv[4] = {w.x, w.y, w.z, w.w};
            #pragma unroll
            for (int i = 0; i < 4; i++)
                #pragma unroll
                for (int j = 0; j < 4; j++)
                    acc[i][j] += avv[i] * wvv[j];
        }
        __syncthreads();
    }
    #pragma unroll
    for (int i = 0; i < 4; i++) {
        int m = m0 + ty*4 + i;
        #pragma unroll
        for (int j = 0; j < 4; j++) {
            int n = n0 + tx*4 + j;
            C[(size_t)m * N + n] = acc[i][j] + bias[n];
        }
    }
}

__global__ void compute_tvec(const float* __restrict__ fc2_w, const float* __restrict__ fc1_b,
                             const float* __restrict__ fc2_b, float* __restrict__ tvec)
{
    int g = (blockIdx.x * blockDim.x + threadIdx.x) >> 5;
    int lane = threadIdx.x & 31;
    if (g >= HID) return;
    const float* w = fc2_w + (size_t)g * DIM2;
    float s = 0.f;
    for (int d = lane; d < DIM2; d += 32) s += w[d] * fc1_b[d];
    #pragma unroll
    for (int o = 16; o; o >>= 1) s += __shfl_down_sync(0xffffffffu, s, o);
    if (!lane) tvec[g] = s + fc2_b[g];
}

__global__ void compute_beff(const float* __restrict__ w_ih, const float* __restrict__ tvec,
                             const float* __restrict__ b_ih, float* __restrict__ beff)
{
    int g = (blockIdx.x * blockDim.x + threadIdx.x) >> 5;
    int lane = threadIdx.x & 31;
    if (g >= G3) return;
    const float* w = w_ih + (size_t)g * HID;
    float s = 0.f;
    for (int d = lane; d < HID; d += 32) s += w[d] * tvec[d];
    #pragma unroll
    for (int o = 16; o; o >>= 1) s += __shfl_down_sync(0xffffffffu, s, o);
    if (!lane) beff[g] = s + b_ih[g];
}

__global__ void zero_bar(int* __restrict__ bar)
{
    bar[threadIdx.x] = 0;
}

// ======================= split / re-layout kernels =========================
__global__ void split_tiled(const float* __restrict__ s, half* __restrict__ dst,
                            int K, int n)
{
    int i = (blockIdx.x * blockDim.x + threadIdx.x) * 4;
    if (i >= n) return;
    int r = i / K, c = i % K;
    float4 v = *(const float4*)(s + i);
    half h[4], l[4];
    split2(v.x, h[0], l[0]); split2(v.y, h[1], l[1]);
    split2(v.z, h[2], l[2]); split2(v.w, h[3], l[3]);
    size_t base = (((size_t)(r >> 7) * (K >> 5) + (c >> 5)) * 2) * 5120
                + (size_t)(r & 127) * 40 + (c & 31);
    *(half2*)(dst + base)        = __halves2half2(h[0], h[1]);
    *(half2*)(dst + base + 2)    = __halves2half2(h[2], h[3]);
    *(half2*)(dst + base + 5120) = __halves2half2(l[0], l[1]);
    *(half2*)(dst + base + 5122) = __halves2half2(l[2], l[3]);
}

// w_hh -> persistent layouts: hi [jt][kt][48][40]; lo (n gate only) [jt][kt][16][40]
__global__ void split_whh_hl(const float* __restrict__ s, half* __restrict__ dh,
                             half* __restrict__ dl)
{
    int i = (blockIdx.x * blockDim.x + threadIdx.x) * 4;
    int rw = i >> 10, c = i & 1023;
    int g = rw >> 10, j = rw & 1023;
    int jt = j >> 4, jr = j & 15, kt = c >> 5, kc = c & 31;
    float4 v = *(const float4*)(s + i);
    half h[4], l[4];
    split2(v.x, h[0], l[0]); split2(v.y, h[1], l[1]);
    split2(v.z, h[2], l[2]); split2(v.w, h[3], l[3]);
    size_t hb = ((size_t)jt * 32 + kt) * 1920 + (size_t)(g * 16 + jr) * 40 + kc;
    *(half2*)(dh + hb)     = __halves2half2(h[0], h[1]);
    *(half2*)(dh + hb + 2) = __halves2half2(h[2], h[3]);
    if (g == 2) {
        size_t lb = ((size_t)jt * 32 + kt) * 640 + (size_t)jr * 40 + kc;
        *(half2*)(dl + lb)     = __halves2half2(l[0], l[1]);
        *(half2*)(dl + lb + 2) = __halves2half2(l[2], l[3]);
    }
}

// h0 -> g_hbuf buffer 0: [mt][kt][plane][128][40]
__global__ void split_h0_b(const float* __restrict__ s, half* __restrict__ hbuf)
{
    int i = (blockIdx.x * blockDim.x + threadIdx.x) * 4;
    int r = i >> 10, c = i & 1023;
    int mt = r >> 7, rl = r & 127, kt = c >> 5, kc = c & 31;
    float4 v = *(const float4*)(s + i);
    half h[4], l[4];
    split2(v.x, h[0], l[0]); split2(v.y, h[1], l[1]);
    split2(v.z, h[2], l[2]); split2(v.w, h[3], l[3]);
    size_t base = (((size_t)mt * 32 + kt) * 2) * 5120 + (size_t)rl * 40 + kc;
    *(half2*)(hbuf + base)        = __halves2half2(h[0], h[1]);
    *(half2*)(hbuf + base + 2)    = __halves2half2(h[2], h[3]);
    *(half2*)(hbuf + base + 5120) = __halves2half2(l[0], l[1]);
    *(half2*)(hbuf + base + 5122) = __halves2half2(l[2], l[3]);
}

// final h -> hn_out f32 + relu(h) GEMM-A tiled (K=1024)
__global__ void finalize_h(const float* __restrict__ hsrc, float* __restrict__ out_hn,
                           half* __restrict__ rht)
{
    int i = (blockIdx.x * blockDim.x + threadIdx.x) * 4;
    int r = i >> 10, c = i & 1023;
    float4 v = *(const float4*)(hsrc + i);
    *(float4*)(out_hn + i) = v;
    float rv[4] = { fmaxf(v.x,0.f), fmaxf(v.y,0.f), fmaxf(v.z,0.f), fmaxf(v.w,0.f) };
    half h[4], l[4];
    #pragma unroll
    for (int k = 0; k < 4; k++) split2(rv[k], h[k], l[k]);
    size_t base = (((size_t)(r >> 7) * 32 + (c >> 5)) * 2) * 5120
                + (size_t)(r & 127) * 40 + (c & 31);
    *(half2*)(rht + base)        = __halves2half2(h[0], h[1]);
    *(half2*)(rht + base + 2)    = __halves2half2(h[2], h[3]);
    *(half2*)(rht + base + 5120) = __halves2half2(l[0], l[1]);
    *(half2*)(rht + base + 5122) = __halves2half2(l[2], l[3]);
}

// single extern dynamic-smem declaration for ALL kernels
extern __shared__ __align__(16) unsigned char dynsmem[];

// ======================= bulk-pipelined fp16x3 GEMM ========================
// Main term f32-accum; two correction terms f16-accum (added in epilogue).
// BM=BN=128, BK=32, 256 thr, 3-stage.
// GILAYOUT: write to gi layout [t][jt][b][48] (m = b*256+t, n = g*1024+j).
template<bool RELU, bool GILAYOUT>
__global__ __launch_bounds__(256)
void gemm_h3b(const half* __restrict__ At, const half* __restrict__ Wt,
              const float* __restrict__ bias, float* __restrict__ C,
              int N, int KT)
{
    half* sA = (half*)dynsmem;
    half* sW = (half*)dynsmem + 3 * 10240;
    __shared__ __align__(8) unsigned long long mbar[3];

    const int tid = threadIdx.x, wid = tid >> 5, lane = tid & 31;
    const int n0 = blockIdx.x * 128, m0 = blockIdx.y * 128;
    const int wm = wid & 3, wn = wid >> 2;
    const half* Ab = At + (size_t)blockIdx.y * KT * 10240;
    const half* Wb = Wt + (size_t)blockIdx.x * KT * 10240;

    if (tid == 0)
        for (int s = 0; s < 3; s++) MBAR_INIT(saddr(&mbar[s]), 1);
    __syncthreads();
    if (tid == 0) {
        for (int s = 0; s < 2 && s < KT; s++) {
            EXPECT_TX(saddr(&mbar[s]), 40960);
            BULK_G2S(saddr(sA + s*10240), Ab + (size_t)s*10240, 20480, saddr(&mbar[s]));
            BULK_G2S(saddr(sW + s*10240), Wb + (size_t)s*10240, 20480, saddr(&mbar[s]));
        }
    }

    float acc[2][8][4] = {};
    unsigned cor[2][8][2];
    #pragma unroll
    for (int a = 0; a < 2; a++)
        #pragma unroll
        for (int b = 0; b < 8; b++) { cor[a][b][0] = 0u; cor[a][b][1] = 0u; }

    const unsigned aOff = (unsigned)((wm*32 + (lane & 15)) * 80 + ((lane >> 4) & 1) * 16);
    const unsigned bOff = (unsigned)((wn*64 + (lane & 7) + ((lane >> 4) & 1) * 8) * 80
                                     + ((lane >> 3) & 1) * 16);
    const unsigned baseA = saddr(sA), baseW = saddr(sW);

    for (int kt = 0; kt < KT; kt++) {
        __syncthreads();
        if (tid == 0) {
            int ks = kt + 2;
            if (ks < KT) {
                int sl = ks % 3;
                EXPECT_TX(saddr(&mbar[sl]), 40960);
                BULK_G2S(saddr(sA + sl*10240), Ab + (size_t)ks*10240, 20480, saddr(&mbar[sl]));
                BULK_G2S(saddr(sW + sl*10240), Wb + (size_t)ks*10240, 20480, saddr(&mbar[sl]));
            }
        }
        const int slot = kt % 3, par = (kt / 3) & 1;
        MBWAIT(saddr(&mbar[slot]), par);

        const unsigned bAh = baseA + slot * 20480;
        const unsigned bAl = bAh + 10240;
        const unsigned bWh = baseW + slot * 20480;
        const unsigned bWl = bWh + 10240;

        #pragma unroll
        for (int kk = 0; kk < 2; kk++) {
            unsigned ah[2][4], al[2][4];
            #pragma unroll
            for (int mt = 0; mt < 2; mt++) {
                unsigned off = aOff + mt * (16*80) + kk * 32;
                ldsm4(ah[mt], bAh + off);
                ldsm4(al[mt], bAl + off);
            }
            #pragma unroll
            for (int p4 = 0; p4 < 4; p4++) {
                unsigned off = bOff + p4 * (16*80) + kk * 32;
                unsigned bh[4], bl[4];
                ldsm4(bh, bWh + off);
                ldsm4(bl, bWl + off);
                #pragma unroll
                for (int t2 = 0; t2 < 2; t2++) {
                    int nt = p4 * 2 + t2;
                    #pragma unroll
                    for (int mt = 0; mt < 2; mt++) {
                        mma16(acc[mt][nt], ah[mt], bh + t2*2);        // main, f32
                        mma16h(cor[mt][nt], ah[mt], bl + t2*2);       // corr, f16
                        mma16h(cor[mt][nt], al[mt], bh + t2*2);       // corr, f16
                    }
                }
            }
        }
    }

    #pragma unroll
    for (int mt = 0; mt < 2; mt++)
        #pragma unroll
        for (int nt = 0; nt < 8; nt++) {
            int n = n0 + wn*64 + nt*8 + (lane & 3) * 2;
            float bx = bias[n], by = bias[n + 1];
            #pragma unroll
            for (int h2 = 0; h2 < 2; h2++) {
                int m = m0 + wm*32 + mt*16 + (lane >> 2) + h2*8;
                float vx = acc[mt][nt][h2*2+0] + corr_lo(cor[mt][nt][h2]) + bx;
                float vy = acc[mt][nt][h2*2+1] + corr_hi(cor[mt][nt][h2]) + by;
                if (RELU) { vx = fmaxf(vx, 0.f); vy = fmaxf(vy, 0.f); }
                float2 v; v.x = vx; v.y = vy;
                if (GILAYOUT) {
                    int b = m >> 8, tt = m & 255;
                    int g = n >> 10, j = n & 1023;
                    size_t addr = (((size_t)tt * 64 + (j >> 4)) * 256 + b) * 48
                                + g * 16 + (j & 15);
                    *(float2*)(C + addr) = v;
                } else {
                    *(float2*)(C + (size_t)m * N + n) = v;
                }
            }
        }
}

// ======================= persistent GRU kernel ==============================
// Grid (jt=64, mt=2) = 128 blocks, 256 thr. One launch covers all 256 steps.
// 5 mmas per kk/t2 group: r = main; z = main; n = main + h-lo + W-lo.
// SMEM: W_hi resident (122880B) | 3 stages (H 20480 + Wlo(n) 1280) | gi 24576B.
#define STG_SZ   21760
#define OFF_STG  122880
#define OFF_GI   (122880 + 3*STG_SZ)        // 188160
#define PERS_SMEM (OFF_GI + 24576)          // 212736

__global__ __launch_bounds__(256)
void gru_persist(const float* __restrict__ hn,
                 const half* __restrict__ whhH, const half* __restrict__ whhL,
                 const float* __restrict__ gi2, const float* __restrict__ b_hh,
                 half* __restrict__ hbuf, float* __restrict__ hf_final,
                 int* __restrict__ bar)
{
    __shared__ __align__(8) unsigned long long mbar[5];
    const unsigned sb = saddr(dynsmem);
    const int tid = threadIdx.x, w = tid >> 5, lane = tid & 31;
    const int jt = blockIdx.x, mt = blockIdx.y;

    if (tid == 0)
        for (int i = 0; i < 5; i++) MBAR_INIT(saddr(&mbar[i]), 1);
    __syncthreads();
    const unsigned mbW = saddr(&mbar[0]);
    const unsigned mbS = saddr(&mbar[1]);   // +8*s
    const unsigned mbG = saddr(&mbar[4]);

    // resident W_hi load (once)
    if (tid == 0) {
        EXPECT_TX(mbW, 122880);
        BULK_G2S(sb, (const char*)whhH + (size_t)jt * 122880, 122880, mbW);
    }

    // per-thread output coordinates
    const int mrow = w * 16 + (lane >> 2);        // + h2*8
    const int jl0  = (lane & 3) * 2;              // + t2*8 (+c)
    float hprev[8];
    float bb[12];
    #pragma unroll
    for (int h2 = 0; h2 < 2; h2++)
        #pragma unroll
        for (int t2 = 0; t2 < 2; t2++) {
            int m = mt*128 + mrow + h2*8;
            int j = jt*16 + t2*8 + jl0;
            float2 hv = *(const float2*)(hn + (size_t)m * HID + j);
            hprev[h2*4 + t2*2 + 0] = hv.x;
            hprev[h2*4 + t2*2 + 1] = hv.y;
        }
    #pragma unroll
    for (int g = 0; g < 3; g++)
        #pragma unroll
        for (int t2 = 0; t2 < 2; t2++) {
            float2 bv = *(const float2*)(b_hh + g*HID + jt*16 + t2*8 + jl0);
            bb[g*4 + t2*2 + 0] = bv.x;
            bb[g*4 + t2*2 + 1] = bv.y;
        }

    const unsigned aOff = (unsigned)((w*16 + (lane & 15)) * 80 + ((lane >> 4) & 1) * 16);
    const unsigned bOff = (unsigned)(((lane & 7) + ((lane >> 4) & 1) * 8) * 80
                                     + ((lane >> 3) & 1) * 16);

    int us0 = 0, us1 = 0, us2 = 0;   // per-slot use counters (parity)
    MBWAIT(mbW, 0);

    for (int t = 0; t < T_SZ; t++) {
        const char* Hb = (const char*)hbuf
            + (((size_t)(t & 1) * 2 + mt) * 32) * 20480;
        const char* Lb = (const char*)whhL + (size_t)jt * 32 * 1280;
        if (tid == 0) {
            EXPECT_TX(mbG, 24576);
            BULK_G2S(sb + OFF_GI,
                     (const char*)gi2 + ((((size_t)t * 64 + jt) * 256 + mt*128) * 48) * 4,
                     24576, mbG);
            #pragma unroll
            for (int s = 0; s < 3; s++) {
                EXPECT_TX(mbS + 8*s, STG_SZ);
                BULK_G2S(sb + OFF_STG + s*STG_SZ,         Hb + (size_t)s*20480, 20480, mbS + 8*s);
                BULK_G2S(sb + OFF_STG + s*STG_SZ + 20480, Lb + (size_t)s*1280,  1280,  mbS + 8*s);
            }
        }

        float acc[6][4] = {};
        unsigned cor[2][2];   // n-gate corrections (t2)
        cor[0][0] = cor[0][1] = cor[1][0] = cor[1][1] = 0u;

        int slot = 0;
        for (int kt = 0; kt < 32; kt++) {
            int par;
            if (slot == 0)      { par = us0 & 1; us0++; }
            else if (slot == 1) { par = us1 & 1; us1++; }
            else                { par = us2 & 1; us2++; }
            MBWAIT(mbS + 8*slot, par);

            const unsigned hHi = sb + OFF_STG + slot*STG_SZ;
            const unsigned hLo = hHi + 10240;
            const unsigned wLo = hHi + 20480;
            const unsigned wHi = sb + kt * 3840;

            #pragma unroll
            for (int kk = 0; kk < 2; kk++) {
                unsigned ah[4], al[4];
                ldsm4(ah, hHi + aOff + kk*32);
                ldsm4(al, hLo + aOff + kk*32);
                unsigned br[4], bz[4], bn[4], bln[4];
                ldsm4(br,  wHi + bOff + kk*32);
                ldsm4(bz,  wHi + bOff + 16*80 + kk*32);
                ldsm4(bn,  wHi + bOff + 32*80 + kk*32);
                ldsm4(bln, wLo + bOff + kk*32);
                #pragma unroll
                for (int t2 = 0; t2 < 2; t2++) {
                    // r gate: main only (f32)
                    mma16(acc[0+t2], ah, br + t2*2);
                    // z gate: main only (f32)
                    mma16(acc[2+t2], ah, bz + t2*2);
                    // n gate: main (f32) + h-lo + W-lo (f16)
                    mma16(acc[4+t2], ah, bn + t2*2);
                    mma16h(cor[t2], al, bn + t2*2);
                    mma16h(cor[t2], ah, bln + t2*2);
                }
            }
            __syncthreads();
            if (tid == 0 && kt + 3 < 32) {
                int ks = kt + 3;
                EXPECT_TX(mbS + 8*slot, STG_SZ);
                BULK_G2S(sb + OFF_STG + slot*STG_SZ,         Hb + (size_t)ks*20480, 20480, mbS + 8*slot);
                BULK_G2S(sb + OFF_STG + slot*STG_SZ + 20480, Lb + (size_t)ks*1280,  1280,  mbS + 8*slot);
            }
            slot = (slot == 2) ? 0 : slot + 1;
        }

        // epilogue: gates + state update
        MBWAIT(mbG, t & 1);
        const float* gis = (const float*)(dynsmem + OFF_GI);
        char* ob = (char*)hbuf
            + ((((size_t)((t+1) & 1) * 2 + mt) * 32 + (jt >> 1))) * 20480;
        const int kc0 = (jt & 1) * 16;

        #pragma unroll
        for (int h2 = 0; h2 < 2; h2++) {
            int ml = mrow + h2*8;
            #pragma unroll
            for (int t2 = 0; t2 < 2; t2++) {
                float hh[2];
                #pragma unroll
                for (int c = 0; c < 2; c++) {
                    int fi = h2*2 + c;
                    int jl = t2*8 + jl0 + c;
                    float cn = c ? corr_hi(cor[t2][h2]) : corr_lo(cor[t2][h2]);
                    float rpre = acc[0+t2][fi] + bb[0 + t2*2 + c] + gis[ml*48 + jl];
                    float zpre = acc[2+t2][fi] + bb[4 + t2*2 + c] + gis[ml*48 + 16 + jl];
                    float hnn  = acc[4+t2][fi] + cn + bb[8 + t2*2 + c];
                    float r_ = 1.f / (1.f + expf(-rpre));
                    float z_ = 1.f / (1.f + expf(-zpre));
                    float n_ = tanhf(gis[ml*48 + 32 + jl] + r_ * hnn);
                    int pi = h2*4 + t2*2 + c;
                    float hv = (1.f - z_) * n_ + z_ * hprev[pi];
                    hprev[pi] = hv;
                    hh[c] = hv;
                }
                half a0, b0, a1, b1;
                split2(hh[0], a0, b0);
                split2(hh[1], a1, b1);
                int kc = kc0 + t2*8 + jl0;
                *(half2*)(ob + (size_t)ml*80 + kc*2)         = __halves2half2(a0, a1);
                *(half2*)(ob + 10240 + (size_t)ml*80 + kc*2) = __halves2half2(b0, b1);
                if (t == T_SZ - 1) {
                    float2 fv; fv.x = hh[0]; fv.y = hh[1];
                    *(float2*)(hf_final + (size_t)(mt*128 + ml) * HID
                               + jt*16 + t2*8 + jl0) = fv;
                }
            }
        }

        // inter-step barrier (per m-group of 64 blocks)
        if (t < T_SZ - 1) {
            __threadfence();
            __syncthreads();
            if (tid == 0) {
                int* cnt = bar + mt * T_SZ + t;
                atomicAdd(cnt, 1);
                while (atomicAdd(cnt, 0) < 64) { }
            }
            __syncthreads();
        }
    }
}

// ======================= tail ==============================================
__global__ __launch_bounds__(128)
void heads_kernel(const float* __restrict__ o3, const int* __restrict__ cult,
                  const float* __restrict__ hw, const float* __restrict__ hb,
                  float* __restrict__ outp)
{
    int b = blockIdx.x;
    int c = cult[b];
    __shared__ float sv[DIM2];
    for (int i = threadIdx.x; i < DIM2; i += blockDim.x)
        sv[i] = o3[(size_t)b * DIM2 + i];
    __syncthreads();
    int o = threadIdx.x >> 3, l = threadIdx.x & 7;
    const float* w = hw + ((size_t)c * OUT_DIM + o) * DIM2;
    float s = 0.f;
    for (int d = l; d < DIM2; d += 8) s += sv[d] * w[d];
    s += __shfl_down_sync(0xffffffffu, s, 4);
    s += __shfl_down_sync(0xffffffffu, s, 2);
    s += __shfl_down_sync(0xffffffffu, s, 1);
    if (l == 0) outp[b * OUT_DIM + o] = s + hb[c * OUT_DIM + o];
}

// ======================= launch ============================================
#define GEMM_SMEM (3*10240*2*2)   // 122880 B

extern "C" void kernel_launch(void* const* d_in, const int* in_sizes, int n_in,
                              void* d_out, int out_size)
{
    const float* input = (const float*)d_in[0];
    const float* hn    = (const float*)d_in[1];
    const int*   cult  = (const int*)  d_in[2];
    const float* fc1_w = (const float*)d_in[3];
    const float* fc1_b = (const float*)d_in[4];
    const float* fc2_w = (const float*)d_in[5];
    const float* fc2_b = (const float*)d_in[6];
    const float* w_ih  = (const float*)d_in[7];
    const float* w_hh  = (const float*)d_in[8];
    const float* b_ih  = (const float*)d_in[9];
    const float* b_hh  = (const float*)d_in[10];
    const float* fc3_w = (const float*)d_in[11];
    const float* fc3_b = (const float*)d_in[12];
    const float* hw    = (const float*)d_in[13];
    const float* hb    = (const float*)d_in[14];
    float* outp = (float*)d_out;

    float *gi, *o3, *hf, *fc2T, *fc1T, *T1, *weff, *tvec, *beff, *zb;
    int* bar;
    half *intl, *wefft, *w3t, *rht, *whhH, *whhL, *hbuf;
    cudaGetSymbolAddress((void**)&gi, g_gi);
    cudaGetSymbolAddress((void**)&o3, g_o3);
    cudaGetSymbolAddress((void**)&hf, g_hf);
    cudaGetSymbolAddress((void**)&bar, g_bar);
    cudaGetSymbolAddress((void**)&fc2T, g_fc2T);
    cudaGetSymbolAddress((void**)&fc1T, g_fc1T);
    cudaGetSymbolAddress((void**)&T1, g_T1);
    cudaGetSymbolAddress((void**)&weff, g_weff);
    cudaGetSymbolAddress((void**)&tvec, g_tvec);
    cudaGetSymbolAddress((void**)&beff, g_beff);
    cudaGetSymbolAddress((void**)&zb, g_zbias);
    cudaGetSymbolAddress((void**)&intl, g_int);
    cudaGetSymbolAddress((void**)&wefft, g_wefft);
    cudaGetSymbolAddress((void**)&w3t, g_w3t);
    cudaGetSymbolAddress((void**)&rht, g_rht);
    cudaGetSymbolAddress((void**)&whhH, g_whhH);
    cudaGetSymbolAddress((void**)&whhL, g_whhL);
    cudaGetSymbolAddress((void**)&hbuf, g_hbuf);

    cudaFuncSetAttribute(gemm_h3b<false,true>,
                         cudaFuncAttributeMaxDynamicSharedMemorySize, GEMM_SMEM);
    cudaFuncSetAttribute(gemm_h3b<true,false>,
                         cudaFuncAttributeMaxDynamicSharedMemorySize, GEMM_SMEM);
    cudaFuncSetAttribute(gru_persist,
                         cudaFuncAttributeMaxDynamicSharedMemorySize, PERS_SMEM);

    // fold precompute: W_eff = w_ih @ fc2_w @ fc1_w, b_eff
    transpose_f32<<<dim3(DIM2/32, HID/32), dim3(32,8)>>>(fc2_w, fc2T, HID, DIM2);
    transpose_f32<<<dim3(IN_DIM/32, DIM2/32), dim3(32,8)>>>(fc1_w, fc1T, DIM2, IN_DIM);
    gemm_nt<<<dim3(G3/64, DIM2/64), 256>>>(w_ih, fc2T, zb, T1, G3, DIM2, HID);
    gemm_nt<<<dim3(G3/64, IN_DIM/64), 256>>>(T1, fc1T, zb, weff, G3, IN_DIM, DIM2);
    compute_tvec<<<HID*32/256, 256>>>(fc2_w, fc1_b, fc2_b, tvec);
    compute_beff<<<G3*32/256, 256>>>(w_ih, tvec, b_ih, beff);
    zero_bar<<<1, 2*T_SZ>>>(bar);

    // splits
    split_tiled<<<MT*IN_DIM/1024, 256>>>(input, intl, IN_DIM, MT*IN_DIM);
    split_tiled<<<G3*IN_DIM/1024, 256>>>(weff, wefft, IN_DIM, G3*IN_DIM);
    split_tiled<<<DIM2*HID/1024, 256>>>(fc3_w, w3t, HID, DIM2*HID);
    split_whh_hl<<<G3*HID/1024, 256>>>(w_hh, whhH, whhL);
    split_h0_b<<<B_SZ*HID/1024, 256>>>(hn, hbuf);

    // gi = input @ W_eff^T + b_eff, K=64, layout [t][jt][b][48]
    gemm_h3b<false,true><<<dim3(G3/128, MT/128), 256, GEMM_SMEM>>>(
        intl, wefft, beff, gi, G3, IN_DIM/32);

    // persistent GRU: one launch, 256 steps
    gru_persist<<<dim3(64, 2), 256, PERS_SMEM>>>(
        hn, whhH, whhL, gi, b_hh, hbuf, hf, bar);

    int hn_off = out_size - B_SZ * HID;
    finalize_h<<<B_SZ*HID/1024, 256>>>(hf, outp + hn_off, rht);

    // fc3: relu(h) @ fc3_w^T, relu epilogue
    gemm_h3b<true,false><<<dim3(DIM2/128, B_SZ/128), 256, GEMM_SMEM>>>(
        rht, w3t, fc3_b, o3, DIM2, HID/32);

    heads_kernel<<<B_SZ, 128>>>(o3, cult, hw, hb, outp);
}

// round 17
// speedup vs baseline: 1.2193x; 1.2193x over previous
#include <cuda_runtime.h>
#include <cuda_fp16.h>
#include <math.h>

#define B_SZ 256
#define T_SZ 256
#define IN_DIM 64
#define HID 1024
#define DIM2 512
#define OUT_DIM 16
#define MT (B_SZ*T_SZ)   // 65536
#define G3 (3*HID)       // 3072

// ======================= scratch (device globals) ==========================
__device__ float g_gi[(size_t)MT*G3];       // 805 MB, layout [t][jt(64)][b(256)][48]
__device__ float g_hf[B_SZ*HID];            // final h (f32)
__device__ float g_o3[B_SZ*DIM2];
__device__ int   g_bar[2*T_SZ];             // per-(mt,step) barrier counters

// fold precompute scratch (fp32)
__device__ float g_fc2T[DIM2*HID];
__device__ float g_fc1T[IN_DIM*DIM2];
__device__ float g_T1[(size_t)G3*DIM2];
__device__ float g_weff[G3*IN_DIM];
__device__ float g_tvec[HID];
__device__ float g_beff[G3];
__device__ float g_zbias[DIM2];             // stays zero

// GEMM-geometry split tiles: [tile(128 rows)][stage(k/32)][plane(2)][128][40]
__device__ __align__(128) half g_int  [(size_t)512*2*10240];   // input (K=64)
__device__ __align__(128) half g_wefft[(size_t)24*2*10240];    // W_eff (K=64)
__device__ __align__(128) half g_w3t  [(size_t)4*32*10240];    // fc3_w (K=1024)
__device__ __align__(128) half g_rht  [(size_t)2*32*10240];    // relu(h)
// persistent-GRU weight layouts
__device__ __align__(128) half g_whhH[(size_t)64*32*1920];     // [jt][kt][48][40] hi
__device__ __align__(128) half g_whhL[(size_t)64*32*1280];     // [jt][kt][32][40] lo (z,n)
// h split-plane ping-pong: [buf(2)][mt(2)][kt(32)][plane(2)][128][40]
__device__ __align__(128) half g_hbuf[(size_t)2*2*32*2*128*40];

// ======================= PTX helpers =======================================
__device__ __forceinline__ unsigned saddr(const void* p) {
    return (unsigned)__cvta_generic_to_shared(p);
}
#define MBAR_INIT(mb, cnt) \
    asm volatile("mbarrier.init.shared.b64 [%0], %1;" :: "r"(mb), "r"(cnt) : "memory")
#define EXPECT_TX(mb, bytes) \
    asm volatile("mbarrier.arrive.expect_tx.shared.b64 _, [%0], %1;" :: "r"(mb), "r"(bytes) : "memory")
#define BULK_G2S(dst, src, bytes, mb) \
    asm volatile("cp.async.bulk.shared::cluster.global.mbarrier::complete_tx::bytes [%0], [%1], %2, [%3];" \
        :: "r"(dst), "l"(src), "r"(bytes), "r"(mb) : "memory")
#define MBWAIT(mb, ph) do { unsigned _d = 0; while (!_d) { \
    asm volatile("{\n\t.reg .pred p;\n\t" \
        "mbarrier.try_wait.parity.acquire.cta.shared::cta.b64 p, [%1], %2, 0x989680;\n\t" \
        "selp.b32 %0, 1, 0, p;\n\t}" \
        : "=r"(_d) : "r"(mb), "r"(ph)); } } while (0)

// f32-accumulate HMMA
__device__ __forceinline__ void mma16(float* c, const unsigned* a, const unsigned* b) {
    asm volatile("mma.sync.aligned.m16n8k16.row.col.f32.f16.f16.f32 "
        "{%0,%1,%2,%3}, {%4,%5,%6,%7}, {%8,%9}, {%0,%1,%2,%3};"
        : "+f"(c[0]), "+f"(c[1]), "+f"(c[2]), "+f"(c[3])
        : "r"(a[0]), "r"(a[1]), "r"(a[2]), "r"(a[3]), "r"(b[0]), "r"(b[1]));
}
// f16-accumulate HMMA (for small correction terms)
__device__ __forceinline__ void mma16h(unsigned* c, const unsigned* a, const unsigned* b) {
    asm volatile("mma.sync.aligned.m16n8k16.row.col.f16.f16.f16.f16 "
        "{%0,%1}, {%2,%3,%4,%5}, {%6,%7}, {%0,%1};"
        : "+r"(c[0]), "+r"(c[1])
        : "r"(a[0]), "r"(a[1]), "r"(a[2]), "r"(a[3]), "r"(b[0]), "r"(b[1]));
}
__device__ __forceinline__ void ldsm4(unsigned* r, unsigned addr) {
    asm volatile("ldmatrix.sync.aligned.m8n8.x4.shared.b16 {%0,%1,%2,%3}, [%4];"
        : "=r"(r[0]), "=r"(r[1]), "=r"(r[2]), "=r"(r[3]) : "r"(addr));
}
__device__ __forceinline__ void split2(float x, half& hi, half& lo) {
    hi = __float2half_rn(x);
    lo = __float2half_rn(x - __half2float(hi));
}
__device__ __forceinline__ float corr_lo(unsigned u) {
    __half2 h = *(__half2*)&u; return __low2float(h);
}
__device__ __forceinline__ float corr_hi(unsigned u) {
    __half2 h = *(__half2*)&u; return __high2float(h);
}

// ======================= fold precompute kernels ===========================
__global__ void transpose_f32(const float* __restrict__ s, float* __restrict__ d,
                              int R, int C)
{
    __shared__ float tile[32][33];
    int c0 = blockIdx.x * 32, r0 = blockIdx.y * 32;
    int x = threadIdx.x, y = threadIdx.y;
    #pragma unroll
    for (int i = y; i < 32; i += 8)
        tile[i][x] = s[(size_t)(r0 + i) * C + c0 + x];
    __syncthreads();
    #pragma unroll
    for (int i = y; i < 32; i += 8)
        d[(size_t)(c0 + i) * R + r0 + x] = tile[x][i];
}

__global__ __launch_bounds__(256)
void gemm_nt(const float* __restrict__ A, const float* __restrict__ W,
             const float* __restrict__ bias, float* __restrict__ C,
             int M, int N, int K)
{
    __shared__ float As[16][68];
    __shared__ float Ws[16][68];
    const int tid = threadIdx.x;
    const int m0 = blockIdx.x * 64, n0 = blockIdx.y * 64;
    const int tx = tid & 15, ty = tid >> 4;
    float acc[4][4] = {};
    const int ar = tid >> 2;
    const int ak = (tid & 3) * 4;
    const float* Aptr = A + (size_t)(m0 + ar) * K + ak;
    const float* Wptr = W + (size_t)(n0 + ar) * K + ak;
    for (int k0 = 0; k0 < K; k0 += 16) {
        float4 av = *(const float4*)(Aptr + k0);
        float4 wv = *(const float4*)(Wptr + k0);
        As[ak+0][ar] = av.x; As[ak+1][ar] = av.y; As[ak+2][ar] = av.z; As[ak+3][ar] = av.w;
        Ws[ak+0][ar] = wv.x; Ws[ak+1][ar] = wv.y; Ws[ak+2][ar] = wv.z; Ws[ak+3][ar] = wv.w;
        __syncthreads();
        #pragma unroll
        for (int k = 0; k < 16; k++) {
            float4 a = *(const float4*)&As[k][ty*4];
            float4 w = *(const float4*)&Ws[k][tx*4];
            float avv[4] = {a.x, a.y, a.z, a.w};
            float wvv[4] = {w.x, w.y, w.z, w.w};
            #pragma unroll
            for (int i = 0; i < 4; i++)
                #pragma unroll
                for (int j = 0; j < 4; j++)
                    acc[i][j] += avv[i] * wvv[j];
        }
        __syncthreads();
    }
    #pragma unroll
    for (int i = 0; i < 4; i++) {
        int m = m0 + ty*4 + i;
        #pragma unroll
        for (int j = 0; j < 4; j++) {
            int n = n0 + tx*4 + j;
            C[(size_t)m * N + n] = acc[i][j] + bias[n];
        }
    }
}

__global__ void compute_tvec(const float* __restrict__ fc2_w, const float* __restrict__ fc1_b,
                             const float* __restrict__ fc2_b, float* __restrict__ tvec)
{
    int g = (blockIdx.x * blockDim.x + threadIdx.x) >> 5;
    int lane = threadIdx.x & 31;
    if (g >= HID) return;
    const float* w = fc2_w + (size_t)g * DIM2;
    float s = 0.f;
    for (int d = lane; d < DIM2; d += 32) s += w[d] * fc1_b[d];
    #pragma unroll
    for (int o = 16; o; o >>= 1) s += __shfl_down_sync(0xffffffffu, s, o);
    if (!lane) tvec[g] = s + fc2_b[g];
}

__global__ void compute_beff(const float* __restrict__ w_ih, const float* __restrict__ tvec,
                             const float* __restrict__ b_ih, float* __restrict__ beff)
{
    int g = (blockIdx.x * blockDim.x + threadIdx.x) >> 5;
    int lane = threadIdx.x & 31;
    if (g >= G3) return;
    const float* w = w_ih + (size_t)g * HID;
    float s = 0.f;
    for (int d = lane; d < HID; d += 32) s += w[d] * tvec[d];
    #pragma unroll
    for (int o = 16; o; o >>= 1) s += __shfl_down_sync(0xffffffffu, s, o);
    if (!lane) beff[g] = s + b_ih[g];
}

__global__ void zero_bar(int* __restrict__ bar)
{
    bar[threadIdx.x] = 0;
}

// ======================= split / re-layout kernels =========================
__global__ void split_tiled(const float* __restrict__ s, half* __restrict__ dst,
                            int K, int n)
{
    int i = (blockIdx.x * blockDim.x + threadIdx.x) * 4;
    if (i >= n) return;
    int r = i / K, c = i % K;
    float4 v = *(const float4*)(s + i);
    half h[4], l[4];
    split2(v.x, h[0], l[0]); split2(v.y, h[1], l[1]);
    split2(v.z, h[2], l[2]); split2(v.w, h[3], l[3]);
    size_t base = (((size_t)(r >> 7) * (K >> 5) + (c >> 5)) * 2) * 5120
                + (size_t)(r & 127) * 40 + (c & 31);
    *(half2*)(dst + base)        = __halves2half2(h[0], h[1]);
    *(half2*)(dst + base + 2)    = __halves2half2(h[2], h[3]);
    *(half2*)(dst + base + 5120) = __halves2half2(l[0], l[1]);
    *(half2*)(dst + base + 5122) = __halves2half2(l[2], l[3]);
}

// w_hh -> persistent layouts: hi [jt][kt][48][40]; lo (z,n) [jt][kt][32][40]
__global__ void split_whh_hl(const float* __restrict__ s, half* __restrict__ dh,
                             half* __restrict__ dl)
{
    int i = (blockIdx.x * blockDim.x + threadIdx.x) * 4;
    int rw = i >> 10, c = i & 1023;
    int g = rw >> 10, j = rw & 1023;
    int jt = j >> 4, jr = j & 15, kt = c >> 5, kc = c & 31;
    float4 v = *(const float4*)(s + i);
    half h[4], l[4];
    split2(v.x, h[0], l[0]); split2(v.y, h[1], l[1]);
    split2(v.z, h[2], l[2]); split2(v.w, h[3], l[3]);
    size_t hb = ((size_t)jt * 32 + kt) * 1920 + (size_t)(g * 16 + jr) * 40 + kc;
    *(half2*)(dh + hb)     = __halves2half2(h[0], h[1]);
    *(half2*)(dh + hb + 2) = __halves2half2(h[2], h[3]);
    if (g >= 1) {
        size_t lb = ((size_t)jt * 32 + kt) * 1280 + (size_t)((g - 1) * 16 + jr) * 40 + kc;
        *(half2*)(dl + lb)     = __halves2half2(l[0], l[1]);
        *(half2*)(dl + lb + 2) = __halves2half2(l[2], l[3]);
    }
}

// h0 -> g_hbuf buffer 0: [mt][kt][plane][128][40]
__global__ void split_h0_b(const float* __restrict__ s, half* __restrict__ hbuf)
{
    int i = (blockIdx.x * blockDim.x + threadIdx.x) * 4;
    int r = i >> 10, c = i & 1023;
    int mt = r >> 7, rl = r & 127, kt = c >> 5, kc = c & 31;
    float4 v = *(const float4*)(s + i);
    half h[4], l[4];
    split2(v.x, h[0], l[0]); split2(v.y, h[1], l[1]);
    split2(v.z, h[2], l[2]); split2(v.w, h[3], l[3]);
    size_t base = (((size_t)mt * 32 + kt) * 2) * 5120 + (size_t)rl * 40 + kc;
    *(half2*)(hbuf + base)        = __halves2half2(h[0], h[1]);
    *(half2*)(hbuf + base + 2)    = __halves2half2(h[2], h[3]);
    *(half2*)(hbuf + base + 5120) = __halves2half2(l[0], l[1]);
    *(half2*)(hbuf + base + 5122) = __halves2half2(l[2], l[3]);
}

// final h -> hn_out f32 + relu(h) GEMM-A tiled (K=1024)
__global__ void finalize_h(const float* __restrict__ hsrc, float* __restrict__ out_hn,
                           half* __restrict__ rht)
{
    int i = (blockIdx.x * blockDim.x + threadIdx.x) * 4;
    int r = i >> 10, c = i & 1023;
    float4 v = *(const float4*)(hsrc + i);
    *(float4*)(out_hn + i) = v;
    float rv[4] = { fmaxf(v.x,0.f), fmaxf(v.y,0.f), fmaxf(v.z,0.f), fmaxf(v.w,0.f) };
    half h[4], l[4];
    #pragma unroll
    for (int k = 0; k < 4; k++) split2(rv[k], h[k], l[k]);
    size_t base = (((size_t)(r >> 7) * 32 + (c >> 5)) * 2) * 5120
                + (size_t)(r & 127) * 40 + (c & 31);
    *(half2*)(rht + base)        = __halves2half2(h[0], h[1]);
    *(half2*)(rht + base + 2)    = __halves2half2(h[2], h[3]);
    *(half2*)(rht + base + 5120) = __halves2half2(l[0], l[1]);
    *(half2*)(rht + base + 5122) = __halves2half2(l[2], l[3]);
}

// single extern dynamic-smem declaration for ALL kernels
extern __shared__ __align__(16) unsigned char dynsmem[];

// ======================= bulk-pipelined fp16x3 GEMM ========================
// Main term f32-accum; two correction terms f16-accum (added in epilogue).
// BM=BN=128, BK=32, 256 thr, 3-stage.
// GILAYOUT: write to gi layout [t][jt][b][48] (m = b*256+t, n = g*1024+j).
template<bool RELU, bool GILAYOUT>
__global__ __launch_bounds__(256)
void gemm_h3b(const half* __restrict__ At, const half* __restrict__ Wt,
              const float* __restrict__ bias, float* __restrict__ C,
              int N, int KT)
{
    half* sA = (half*)dynsmem;
    half* sW = (half*)dynsmem + 3 * 10240;
    __shared__ __align__(8) unsigned long long mbar[3];

    const int tid = threadIdx.x, wid = tid >> 5, lane = tid & 31;
    const int n0 = blockIdx.x * 128, m0 = blockIdx.y * 128;
    const int wm = wid & 3, wn = wid >> 2;
    const half* Ab = At + (size_t)blockIdx.y * KT * 10240;
    const half* Wb = Wt + (size_t)blockIdx.x * KT * 10240;

    if (tid == 0)
        for (int s = 0; s < 3; s++) MBAR_INIT(saddr(&mbar[s]), 1);
    __syncthreads();
    if (tid == 0) {
        for (int s = 0; s < 2 && s < KT; s++) {
            EXPECT_TX(saddr(&mbar[s]), 40960);
            BULK_G2S(saddr(sA + s*10240), Ab + (size_t)s*10240, 20480, saddr(&mbar[s]));
            BULK_G2S(saddr(sW + s*10240), Wb + (size_t)s*10240, 20480, saddr(&mbar[s]));
        }
    }

    float acc[2][8][4] = {};
    unsigned cor[2][8][2];
    #pragma unroll
    for (int a = 0; a < 2; a++)
        #pragma unroll
        for (int b = 0; b < 8; b++) { cor[a][b][0] = 0u; cor[a][b][1] = 0u; }

    const unsigned aOff = (unsigned)((wm*32 + (lane & 15)) * 80 + ((lane >> 4) & 1) * 16);
    const unsigned bOff = (unsigned)((wn*64 + (lane & 7) + ((lane >> 4) & 1) * 8) * 80
                                     + ((lane >> 3) & 1) * 16);
    const unsigned baseA = saddr(sA), baseW = saddr(sW);

    for (int kt = 0; kt < KT; kt++) {
        __syncthreads();
        if (tid == 0) {
            int ks = kt + 2;
            if (ks < KT) {
                int sl = ks % 3;
                EXPECT_TX(saddr(&mbar[sl]), 40960);
                BULK_G2S(saddr(sA + sl*10240), Ab + (size_t)ks*10240, 20480, saddr(&mbar[sl]));
                BULK_G2S(saddr(sW + sl*10240), Wb + (size_t)ks*10240, 20480, saddr(&mbar[sl]));
            }
        }
        const int slot = kt % 3, par = (kt / 3) & 1;
        MBWAIT(saddr(&mbar[slot]), par);

        const unsigned bAh = baseA + slot * 20480;
        const unsigned bAl = bAh + 10240;
        const unsigned bWh = baseW + slot * 20480;
        const unsigned bWl = bWh + 10240;

        #pragma unroll
        for (int kk = 0; kk < 2; kk++) {
            unsigned ah[2][4], al[2][4];
            #pragma unroll
            for (int mt = 0; mt < 2; mt++) {
                unsigned off = aOff + mt * (16*80) + kk * 32;
                ldsm4(ah[mt], bAh + off);
                ldsm4(al[mt], bAl + off);
            }
            #pragma unroll
            for (int p4 = 0; p4 < 4; p4++) {
                unsigned off = bOff + p4 * (16*80) + kk * 32;
                unsigned bh[4], bl[4];
                ldsm4(bh, bWh + off);
                ldsm4(bl, bWl + off);
                #pragma unroll
                for (int t2 = 0; t2 < 2; t2++) {
                    int nt = p4 * 2 + t2;
                    #pragma unroll
                    for (int mt = 0; mt < 2; mt++) {
                        mma16(acc[mt][nt], ah[mt], bh + t2*2);        // main, f32
                        mma16h(cor[mt][nt], ah[mt], bl + t2*2);       // corr, f16
                        mma16h(cor[mt][nt], al[mt], bh + t2*2);       // corr, f16
                    }
                }
            }
        }
    }

    #pragma unroll
    for (int mt = 0; mt < 2; mt++)
        #pragma unroll
        for (int nt = 0; nt < 8; nt++) {
            int n = n0 + wn*64 + nt*8 + (lane & 3) * 2;
            float bx = bias[n], by = bias[n + 1];
            #pragma unroll
            for (int h2 = 0; h2 < 2; h2++) {
                int m = m0 + wm*32 + mt*16 + (lane >> 2) + h2*8;
                float vx = acc[mt][nt][h2*2+0] + corr_lo(cor[mt][nt][h2]) + bx;
                float vy = acc[mt][nt][h2*2+1] + corr_hi(cor[mt][nt][h2]) + by;
                if (RELU) { vx = fmaxf(vx, 0.f); vy = fmaxf(vy, 0.f); }
                float2 v; v.x = vx; v.y = vy;
                if (GILAYOUT) {
                    int b = m >> 8, tt = m & 255;
                    int g = n >> 10, j = n & 1023;
                    size_t addr = (((size_t)tt * 64 + (j >> 4)) * 256 + b) * 48
                                + g * 16 + (j & 15);
                    *(float2*)(C + addr) = v;
                } else {
                    *(float2*)(C + (size_t)m * N + n) = v;
                }
            }
        }
}

// ======================= persistent GRU kernel ==============================
// Grid (jt=64, mt=2) = 128 blocks, 256 thr. One launch covers all 256 steps.
// 6 mmas per kk/t2 group: r = main; z = main + h-lo; n = main + h-lo + W-lo.
// 2 k-chunks per pipeline slot (16 waits/step); gi prefetched into registers.
// SMEM: W_hi resident (122880B) | 2 slots x (2xH 40960 + 2xWlo 5120) = 92160B.
#define SLOT_SZ  46080
#define OFF_STG  122880
#define PERS_SMEM (OFF_STG + 2*SLOT_SZ)     // 215040

__global__ __launch_bounds__(256)
void gru_persist(const float* __restrict__ hn,
                 const half* __restrict__ whhH, const half* __restrict__ whhL,
                 const float* __restrict__ gi2, const float* __restrict__ b_hh,
                 half* __restrict__ hbuf, float* __restrict__ hf_final,
                 int* __restrict__ bar)
{
    __shared__ __align__(8) unsigned long long mbar[3];
    const unsigned sb = saddr(dynsmem);
    const int tid = threadIdx.x, w = tid >> 5, lane = tid & 31;
    const int jt = blockIdx.x, mt = blockIdx.y;

    if (tid == 0)
        for (int i = 0; i < 3; i++) MBAR_INIT(saddr(&mbar[i]), 1);
    __syncthreads();
    const unsigned mbW = saddr(&mbar[0]);
    const unsigned mbS = saddr(&mbar[1]);   // +8*s, 2 slots

    // resident W_hi load (once)
    if (tid == 0) {
        EXPECT_TX(mbW, 122880);
        BULK_G2S(sb, (const char*)whhH + (size_t)jt * 122880, 122880, mbW);
    }

    // per-thread output coordinates
    const int mrow = w * 16 + (lane >> 2);        // + h2*8
    const int jl0  = (lane & 3) * 2;              // + t2*8 (+c)
    float hprev[8];
    float bb[12];
    #pragma unroll
    for (int h2 = 0; h2 < 2; h2++)
        #pragma unroll
        for (int t2 = 0; t2 < 2; t2++) {
            int m = mt*128 + mrow + h2*8;
            int j = jt*16 + t2*8 + jl0;
            float2 hv = *(const float2*)(hn + (size_t)m * HID + j);
            hprev[h2*4 + t2*2 + 0] = hv.x;
            hprev[h2*4 + t2*2 + 1] = hv.y;
        }
    #pragma unroll
    for (int g = 0; g < 3; g++)
        #pragma unroll
        for (int t2 = 0; t2 < 2; t2++) {
            float2 bv = *(const float2*)(b_hh + g*HID + jt*16 + t2*8 + jl0);
            bb[g*4 + t2*2 + 0] = bv.x;
            bb[g*4 + t2*2 + 1] = bv.y;
        }

    const unsigned aOff = (unsigned)((w*16 + (lane & 15)) * 80 + ((lane >> 4) & 1) * 16);
    const unsigned bOff = (unsigned)(((lane & 7) + ((lane >> 4) & 1) * 8) * 80
                                     + ((lane >> 3) & 1) * 16);

    int us0 = 0, us1 = 0;   // per-slot use counters (parity)
    MBWAIT(mbW, 0);

    for (int t = 0; t < T_SZ; t++) {
        const char* Hb = (const char*)hbuf
            + (((size_t)(t & 1) * 2 + mt) * 32) * 20480;
        const char* Lb = (const char*)whhL + (size_t)jt * 32 * 2560;

        // gi prefetch into registers (consumed ~12us later in epilogue)
        const float* gbase = gi2 + ((((size_t)t * 64 + jt) * 256 + mt*128)) * 48;
        float2 gv[2][2][3];
        #pragma unroll
        for (int h2 = 0; h2 < 2; h2++)
            #pragma unroll
            for (int t2 = 0; t2 < 2; t2++)
                #pragma unroll
                for (int g = 0; g < 3; g++)
                    gv[h2][t2][g] = *(const float2*)(gbase
                        + (mrow + h2*8) * 48 + g*16 + t2*8 + jl0);

        if (tid == 0) {
            #pragma unroll
            for (int s = 0; s < 2; s++) {
                EXPECT_TX(mbS + 8*s, SLOT_SZ);
                BULK_G2S(sb + OFF_STG + s*SLOT_SZ,         Hb + (size_t)s*40960, 40960, mbS + 8*s);
                BULK_G2S(sb + OFF_STG + s*SLOT_SZ + 40960, Lb + (size_t)s*5120,  5120,  mbS + 8*s);
            }
        }

        float acc[6][4] = {};
        unsigned cor[4][2];   // [0..1]=z(t2), [2..3]=n(t2)
        #pragma unroll
        for (int i = 0; i < 4; i++) { cor[i][0] = 0u; cor[i][1] = 0u; }

        for (int ktp = 0; ktp < 16; ktp++) {
            const int slot = ktp & 1;
            int par;
            if (slot == 0) { par = us0 & 1; us0++; }
            else           { par = us1 & 1; us1++; }
            MBWAIT(mbS + 8*slot, par);

            #pragma unroll
            for (int kt2 = 0; kt2 < 2; kt2++) {
                const unsigned hHi = sb + OFF_STG + slot*SLOT_SZ + kt2*20480;
                const unsigned hLo = hHi + 10240;
                const unsigned wLo = sb + OFF_STG + slot*SLOT_SZ + 40960 + kt2*2560;
                const unsigned wHi = sb + (ktp*2 + kt2) * 3840;

                #pragma unroll
                for (int kk = 0; kk < 2; kk++) {
                    unsigned ah[4], al[4];
                    ldsm4(ah, hHi + aOff + kk*32);
                    ldsm4(al, hLo + aOff + kk*32);
                    unsigned br[4], bz[4], bn[4], blz[4], bln[4];
                    ldsm4(br,  wHi + bOff + kk*32);
                    ldsm4(bz,  wHi + bOff + 16*80 + kk*32);
                    ldsm4(bn,  wHi + bOff + 32*80 + kk*32);
                    ldsm4(blz, wLo + bOff + kk*32);
                    ldsm4(bln, wLo + bOff + 16*80 + kk*32);
                    #pragma unroll
                    for (int t2 = 0; t2 < 2; t2++) {
                        // r gate: main only (f32)
                        mma16(acc[0+t2], ah, br + t2*2);
                        // z gate: main (f32) + h-lo (f16)
                        mma16(acc[2+t2], ah, bz + t2*2);
                        mma16h(cor[0+t2], al, bz + t2*2);
                        // n gate: main (f32) + h-lo + W-lo (f16)
                        mma16(acc[4+t2], ah, bn + t2*2);
                        mma16h(cor[2+t2], al, bn + t2*2);
                        mma16h(cor[2+t2], ah, bln + t2*2);
                    }
                }
            }
            __syncthreads();
            if (tid == 0 && ktp + 2 < 16) {
                int ks = ktp + 2;
                EXPECT_TX(mbS + 8*slot, SLOT_SZ);
                BULK_G2S(sb + OFF_STG + slot*SLOT_SZ,         Hb + (size_t)ks*40960, 40960, mbS + 8*slot);
                BULK_G2S(sb + OFF_STG + slot*SLOT_SZ + 40960, Lb + (size_t)ks*5120,  5120,  mbS + 8*slot);
            }
        }

        // epilogue: gates + state update (gi from registers)
        char* ob = (char*)hbuf
            + ((((size_t)((t+1) & 1) * 2 + mt) * 32 + (jt >> 1))) * 20480;
        const int kc0 = (jt & 1) * 16;

        #pragma unroll
        for (int h2 = 0; h2 < 2; h2++) {
            int ml = mrow + h2*8;
            #pragma unroll
            for (int t2 = 0; t2 < 2; t2++) {
                float hh[2];
                #pragma unroll
                for (int c = 0; c < 2; c++) {
                    int fi = h2*2 + c;
                    float cz = c ? corr_hi(cor[0+t2][h2]) : corr_lo(cor[0+t2][h2]);
                    float cn = c ? corr_hi(cor[2+t2][h2]) : corr_lo(cor[2+t2][h2]);
                    float gr = c ? gv[h2][t2][0].y : gv[h2][t2][0].x;
                    float gz = c ? gv[h2][t2][1].y : gv[h2][t2][1].x;
                    float gn = c ? gv[h2][t2][2].y : gv[h2][t2][2].x;
                    float rpre = acc[0+t2][fi] + bb[0 + t2*2 + c] + gr;
                    float zpre = acc[2+t2][fi] + cz + bb[4 + t2*2 + c] + gz;
                    float hnn  = acc[4+t2][fi] + cn + bb[8 + t2*2 + c];
                    float r_ = 1.f / (1.f + expf(-rpre));
                    float z_ = 1.f / (1.f + expf(-zpre));
                    float n_ = tanhf(gn + r_ * hnn);
                    int pi = h2*4 + t2*2 + c;
                    float hv = (1.f - z_) * n_ + z_ * hprev[pi];
                    hprev[pi] = hv;
                    hh[c] = hv;
                }
                half a0, b0, a1, b1;
                split2(hh[0], a0, b0);
                split2(hh[1], a1, b1);
                int kc = kc0 + t2*8 + jl0;
                *(half2*)(ob + (size_t)ml*80 + kc*2)         = __halves2half2(a0, a1);
                *(half2*)(ob + 10240 + (size_t)ml*80 + kc*2) = __halves2half2(b0, b1);
                if (t == T_SZ - 1) {
                    float2 fv; fv.x = hh[0]; fv.y = hh[1];
                    *(float2*)(hf_final + (size_t)(mt*128 + ml) * HID
                               + jt*16 + t2*8 + jl0) = fv;
                }
            }
        }

        // inter-step barrier (per m-group of 64 blocks)
        if (t < T_SZ - 1) {
            __threadfence();
            __syncthreads();
            if (tid == 0) {
                int* cnt = bar + mt * T_SZ + t;
                atomicAdd(cnt, 1);
                while (atomicAdd(cnt, 0) < 64) { }
            }
            __syncthreads();
        }
    }
}

// ======================= tail ==============================================
__global__ __launch_bounds__(128)
void heads_kernel(const float* __restrict__ o3, const int* __restrict__ cult,
                  const float* __restrict__ hw, const float* __restrict__ hb,
                  float* __restrict__ outp)
{
    int b = blockIdx.x;
    int c = cult[b];
    __shared__ float sv[DIM2];
    for (int i = threadIdx.x; i < DIM2; i += blockDim.x)
        sv[i] = o3[(size_t)b * DIM2 + i];
    __syncthreads();
    int o = threadIdx.x >> 3, l = threadIdx.x & 7;
    const float* w = hw + ((size_t)c * OUT_DIM + o) * DIM2;
    float s = 0.f;
    for (int d = l; d < DIM2; d += 8) s += sv[d] * w[d];
    s += __shfl_down_sync(0xffffffffu, s, 4);
    s += __shfl_down_sync(0xffffffffu, s, 2);
    s += __shfl_down_sync(0xffffffffu, s, 1);
    if (l == 0) outp[b * OUT_DIM + o] = s + hb[c * OUT_DIM + o];
}

// ======================= launch ============================================
#define GEMM_SMEM (3*10240*2*2)   // 122880 B

extern "C" void kernel_launch(void* const* d_in, const int* in_sizes, int n_in,
                              void* d_out, int out_size)
{
    const float* input = (const float*)d_in[0];
    const float* hn    = (const float*)d_in[1];
    const int*   cult  = (const int*)  d_in[2];
    const float* fc1_w = (const float*)d_in[3];
    const float* fc1_b = (const float*)d_in[4];
    const float* fc2_w = (const float*)d_in[5];
    const float* fc2_b = (const float*)d_in[6];
    const float* w_ih  = (const float*)d_in[7];
    const float* w_hh  = (const float*)d_in[8];
    const float* b_ih  = (const float*)d_in[9];
    const float* b_hh  = (const float*)d_in[10];
    const float* fc3_w = (const float*)d_in[11];
    const float* fc3_b = (const float*)d_in[12];
    const float* hw    = (const float*)d_in[13];
    const float* hb    = (const float*)d_in[14];
    float* outp = (float*)d_out;

    float *gi, *o3, *hf, *fc2T, *fc1T, *T1, *weff, *tvec, *beff, *zb;
    int* bar;
    half *intl, *wefft, *w3t, *rht, *whhH, *whhL, *hbuf;
    cudaGetSymbolAddress((void**)&gi, g_gi);
    cudaGetSymbolAddress((void**)&o3, g_o3);
    cudaGetSymbolAddress((void**)&hf, g_hf);
    cudaGetSymbolAddress((void**)&bar, g_bar);
    cudaGetSymbolAddress((void**)&fc2T, g_fc2T);
    cudaGetSymbolAddress((void**)&fc1T, g_fc1T);
    cudaGetSymbolAddress((void**)&T1, g_T1);
    cudaGetSymbolAddress((void**)&weff, g_weff);
    cudaGetSymbolAddress((void**)&tvec, g_tvec);
    cudaGetSymbolAddress((void**)&beff, g_beff);
    cudaGetSymbolAddress((void**)&zb, g_zbias);
    cudaGetSymbolAddress((void**)&intl, g_int);
    cudaGetSymbolAddress((void**)&wefft, g_wefft);
    cudaGetSymbolAddress((void**)&w3t, g_w3t);
    cudaGetSymbolAddress((void**)&rht, g_rht);
    cudaGetSymbolAddress((void**)&whhH, g_whhH);
    cudaGetSymbolAddress((void**)&whhL, g_whhL);
    cudaGetSymbolAddress((void**)&hbuf, g_hbuf);

    cudaFuncSetAttribute(gemm_h3b<false,true>,
                         cudaFuncAttributeMaxDynamicSharedMemorySize, GEMM_SMEM);
    cudaFuncSetAttribute(gemm_h3b<true,false>,
                         cudaFuncAttributeMaxDynamicSharedMemorySize, GEMM_SMEM);
    cudaFuncSetAttribute(gru_persist,
                         cudaFuncAttributeMaxDynamicSharedMemorySize, PERS_SMEM);

    // fold precompute: W_eff = w_ih @ fc2_w @ fc1_w, b_eff
    transpose_f32<<<dim3(DIM2/32, HID/32), dim3(32,8)>>>(fc2_w, fc2T, HID, DIM2);
    transpose_f32<<<dim3(IN_DIM/32, DIM2/32), dim3(32,8)>>>(fc1_w, fc1T, DIM2, IN_DIM);
    gemm_nt<<<dim3(G3/64, DIM2/64), 256>>>(w_ih, fc2T, zb, T1, G3, DIM2, HID);
    gemm_nt<<<dim3(G3/64, IN_DIM/64), 256>>>(T1, fc1T, zb, weff, G3, IN_DIM, DIM2);
    compute_tvec<<<HID*32/256, 256>>>(fc2_w, fc1_b, fc2_b, tvec);
    compute_beff<<<G3*32/256, 256>>>(w_ih, tvec, b_ih, beff);
    zero_bar<<<1, 2*T_SZ>>>(bar);

    // splits
    split_tiled<<<MT*IN_DIM/1024, 256>>>(input, intl, IN_DIM, MT*IN_DIM);
    split_tiled<<<G3*IN_DIM/1024, 256>>>(weff, wefft, IN_DIM, G3*IN_DIM);
    split_tiled<<<DIM2*HID/1024, 256>>>(fc3_w, w3t, HID, DIM2*HID);
    split_whh_hl<<<G3*HID/1024, 256>>>(w_hh, whhH, whhL);
    split_h0_b<<<B_SZ*HID/1024, 256>>>(hn, hbuf);

    // gi = input @ W_eff^T + b_eff, K=64, layout [t][jt][b][48]
    gemm_h3b<false,true><<<dim3(G3/128, MT/128), 256, GEMM_SMEM>>>(
        intl, wefft, beff, gi, G3, IN_DIM/32);

    // persistent GRU: one launch, 256 steps
    gru_persist<<<dim3(64, 2), 256, PERS_SMEM>>>(
        hn, whhH, whhL, gi, b_hh, hbuf, hf, bar);

    int hn_off = out_size - B_SZ * HID;
    finalize_h<<<B_SZ*HID/1024, 256>>>(hf, outp + hn_off, rht);

    // fc3: relu(h) @ fc3_w^T, relu epilogue
    gemm_h3b<true,false><<<dim3(DIM2/128, B_SZ/128), 256, GEMM_SMEM>>>(
        rht, w3t, fc3_b, o3, DIM2, HID/32);

    heads_kernel<<<B_SZ, 128>>>(o3, cult, hw, hb, outp);
}